// round 13
// baseline (speedup 1.0000x reference)
#include <cuda_runtime.h>
#include <cuda_fp16.h>
#include <cstdint>

#define TABLE_SIZE (1u << 19)
#define HASH_MASK  (TABLE_SIZE - 1u)
#define PRIME1     2654435761u
#define NTH        384          // 256 consumer + 128 producer
#define NCONS      256
#define PTS        64

__device__ __constant__ float RES_TAB[16] = {
    16.f, 20.f, 25.f, 32.f, 40.f, 50.f, 64.f, 80.f,
    101.f, 128.f, 161.f, 203.f, 256.f, 322.f, 406.f, 512.f
};

// ---- smem layout (bytes) ----
#define WS_I8    272             // int8 tile row stride (256 + 16 pad)
#define WS_SMALL 112             // f16 48-k row stride
#define W1I_OFF  0               // [256 n][272] int8 : 69632
#define W0T_OFF  69632           // [256 n][112] f16  : 28672
#define X_OFF    98304           // 2 x [64 m][112] f16 : 14336
#define X_BUFSZ  7168
#define ACTI_OFF 112640          // [64 m][272] int8 : 17408
#define RMAX_OFF 130048          // [64 r][8 w] f32 : 2048
#define CMAX_OFF 132096          // 256 f32 : 1024
#define WSC_OFF  133120          // 256 f32 : 1024
#define RED_OFF  134144          // [64 r][3 c][8 w] f32 : 6144
#define SMEM_BYTES 140288

// named barriers
#define BAR_FULL0   1
#define BAR_FULL1   2
#define BAR_EMPTY0  3
#define BAR_EMPTY1  4
#define BAR_CONS    5

__device__ __forceinline__ void bar_sync(int id, int cnt) {
    asm volatile("bar.sync %0, %1;" :: "r"(id), "r"(cnt) : "memory");
}
__device__ __forceinline__ void bar_arrive(int id, int cnt) {
    asm volatile("bar.arrive %0, %1;" :: "r"(id), "r"(cnt) : "memory");
}
__device__ __forceinline__ uint32_t smem_u32(const void* p) {
    uint32_t a;
    asm("{ .reg .u64 t; cvta.to.shared.u64 t, %1; cvt.u32.u64 %0, t; }" : "=r"(a) : "l"(p));
    return a;
}
__device__ __forceinline__ void ldm_x4(uint32_t* r, uint32_t addr) {
    asm volatile("ldmatrix.sync.aligned.m8n8.x4.shared.b16 {%0,%1,%2,%3}, [%4];"
        : "=r"(r[0]), "=r"(r[1]), "=r"(r[2]), "=r"(r[3]) : "r"(addr));
}
__device__ __forceinline__ void mma_f16h(uint32_t* d, const uint32_t* a, const uint32_t* b) {
    asm volatile("mma.sync.aligned.m16n8k16.row.col.f16.f16.f16.f16 "
        "{%0,%1}, {%2,%3,%4,%5}, {%6,%7}, {%0,%1};"
        : "+r"(d[0]), "+r"(d[1])
        : "r"(a[0]), "r"(a[1]), "r"(a[2]), "r"(a[3]), "r"(b[0]), "r"(b[1]));
}
__device__ __forceinline__ void mma_s8(int32_t* d, const uint32_t* a, const uint32_t* b) {
    asm volatile("mma.sync.aligned.m16n8k32.row.col.s32.s8.s8.s32 "
        "{%0,%1,%2,%3}, {%4,%5,%6,%7}, {%8,%9}, {%0,%1,%2,%3};"
        : "+r"(d[0]), "+r"(d[1]), "+r"(d[2]), "+r"(d[3])
        : "r"(a[0]), "r"(a[1]), "r"(a[2]), "r"(a[3]), "r"(b[0]), "r"(b[1]));
}
__device__ __forceinline__ uint32_t packh(float lo, float hi) {
    __half2 h = __floats2half2_rn(lo, hi);
    return *reinterpret_cast<uint32_t*>(&h);
}
__device__ __forceinline__ uint32_t hmax2_zero(uint32_t v) {
    __half2 h = *reinterpret_cast<__half2*>(&v);
    __half2 z = __floats2half2_rn(0.f, 0.f);
    __half2 r = __hmax2(h, z);
    return *reinterpret_cast<uint32_t*>(&r);
}

extern "C" __global__ void __launch_bounds__(NTH, 1)
ngp_i8_kernel(const float* __restrict__ coords,
              const float* __restrict__ emb,
              const float* __restrict__ W0, const float* __restrict__ b0,
              const float* __restrict__ W1, const float* __restrict__ b1,
              const float* __restrict__ W2, const float* __restrict__ b2,
              float* __restrict__ out, int npts)
{
    extern __shared__ char smem[];
    const uint32_t sb = smem_u32(smem);
    const int t = threadIdx.x;
    const int lane = t & 31;
    const int w = t >> 5;

    float* colmax = (float*)(smem + CMAX_OFF);
    float* wscale = (float*)(smem + WSC_OFF);

    // ---- one-time: W1 column maxes ----
    for (int i = t; i < 256; i += NTH) colmax[i] = 0.f;
    for (int i = t; i < 7168; i += NTH) ((uint32_t*)(smem + W0T_OFF))[i] = 0;
    __syncthreads();
    for (int i = t; i < 256 * 256; i += NTH)
        atomicMax((int*)&colmax[i & 255], __float_as_int(fabsf(W1[i])));
    __syncthreads();
    for (int i = t; i < 256; i += NTH) wscale[i] = colmax[i] * (1.f / 127.f);
    __syncthreads();
    // quantize W1 -> int8 [n][k], stage W0 -> f16
    for (int i = t; i < 256 * 256; i += NTH) {
        const int k = i >> 8, n = i & 255;
        const float cm = colmax[n];
        const float inv = (cm > 0.f) ? 127.f / cm : 0.f;
        *(int8_t*)(smem + W1I_OFF + n * WS_I8 + k) = (int8_t)__float2int_rn(W1[i] * inv);
    }
    for (int i = t; i < 34 * 256; i += NTH) {
        const int k = i >> 8, n = i & 255;
        *(__half*)(smem + W0T_OFF + n * WS_SMALL + k * 2) = __float2half(W0[i]);
    }
    __syncthreads();

    const int ntiles = (npts + PTS - 1) / PTS;

    if (t >= NCONS) {
        // ============ PRODUCERS: encode (2 threads / point, 8 levels) =======
        const int tp = t - NCONS;
        const int p  = tp >> 1;
        const int g  = tp & 1;
        int iter = 0;
        for (int tile = blockIdx.x; tile < ntiles; tile += gridDim.x, iter++) {
            const int b = iter & 1;
            if (iter >= 2) bar_sync(BAR_EMPTY0 + b, NTH);

            const int gp = tile * PTS + p;
            float2 c = make_float2(0.f, 0.f);
            if (gp < npts) c = ((const float2*)coords)[gp];
            const float x = fminf(fmaxf(c.x, -1.f), 1.f);
            const float y = fminf(fmaxf(c.y, -1.f), 1.f);
            char* xrow = smem + X_OFF + b * X_BUFSZ + p * WS_SMALL;

            if (g == 0) {
                *(uint32_t*)xrow = packh(x, y);
            } else {
                #pragma unroll
                for (int z = 0; z < 7; z++) *(uint32_t*)(xrow + 68 + 4 * z) = 0;
            }
            #pragma unroll
            for (int li = 0; li < 8; li++) {
                const int l = g * 8 + li;
                const float res  = RES_TAB[l];
                const float grid = 2.0f / res;
                const float fx = floorf((x + 1.0f) / grid);
                const float fy = floorf((y + 1.0f) / grid);
                const float wx = (x - (fx * grid - 1.0f)) / grid;
                const float wy = (y - (fy * grid - 1.0f)) / grid;
                const unsigned bx = (unsigned)(int)fx;
                const unsigned by = (unsigned)(int)fy;
                const unsigned hy0 = by * PRIME1;
                const unsigned hy1 = (by + 1u) * PRIME1;
                const float2* tabl = (const float2*)emb + (size_t)l * TABLE_SIZE;
                const float2 e00 = tabl[(bx ^ hy0) & HASH_MASK];
                const float2 e01 = tabl[(bx ^ hy1) & HASH_MASK];
                const float2 e10 = tabl[((bx + 1u) ^ hy0) & HASH_MASK];
                const float2 e11 = tabl[((bx + 1u) ^ hy1) & HASH_MASK];
                const float omx = 1.f - wx, omy = 1.f - wy;
                const float f0 = (e00.x * omx + e10.x * wx) * omy + (e01.x * omx + e11.x * wx) * wy;
                const float f1 = (e00.y * omx + e10.y * wx) * omy + (e01.y * omx + e11.y * wx) * wy;
                *(uint32_t*)(xrow + (2 + 2 * l) * 2) = packh(f0, f1);
            }
            bar_arrive(BAR_FULL0 + b, NTH);
        }
    } else {
        // ============ CONSUMERS: 8 warps, each m64 x n32 ====================
        const int arow  = (lane & 7) + ((lane >> 3) & 1) * 8;
        const int akoff = (lane >> 4) * 8;     // f16: 8 elems = 16 bytes
        const int bgrp  = ((lane >> 4) << 3) + (lane & 7);
        const int bk16  = ((lane >> 3) & 1) * 16;
        const int nbase = w * 32;

        const uint32_t xlane0  = sb + X_OFF   + arow * WS_SMALL + akoff * 2;
        const uint32_t w0lane  = sb + W0T_OFF + (nbase + bgrp) * WS_SMALL + bk16;
        const uint32_t ailane  = sb + ACTI_OFF + arow * WS_I8 + (lane >> 4) * 16;
        const uint32_t w1ilane = sb + W1I_OFF + (nbase + bgrp) * WS_I8 + bk16;

        // preloads: b0 (f16x2 C init), b1, W2, W1 col scales
        uint32_t b0p[4];
        float b1r[4][2], w2r[4][2][3], w1sc[4][2];
        #pragma unroll
        for (int j = 0; j < 4; j++) {
            const int n = nbase + j * 8 + 2 * (lane & 3);
            b0p[j] = packh(b0[n], b0[n + 1]);
            b1r[j][0] = b1[n];     b1r[j][1] = b1[n + 1];
            w1sc[j][0] = wscale[n]; w1sc[j][1] = wscale[n + 1];
            #pragma unroll
            for (int c = 0; c < 3; c++) {
                w2r[j][0][c] = W2[n * 3 + c];
                w2r[j][1][c] = W2[(n + 1) * 3 + c];
            }
        }
        const int fr = t / 3;
        const int fc = t - 3 * fr;
        const float b2v = (t < 192) ? b2[fc] : 0.f;
        float* red = (float*)(smem + RED_OFF);
        float* rowmaxs = (float*)(smem + RMAX_OFF);

        int iter = 0;
        for (int tile = blockIdx.x; tile < ntiles; tile += gridDim.x, iter++) {
            const int b = iter & 1;
            bar_sync(BAR_FULL0 + b, NTH);               // encode(tile) done

            // ---------- layer 0: [64,48] @ W0t, f16 accum, bias in C --------
            uint32_t h[4][4][2];
            #pragma unroll
            for (int i = 0; i < 4; i++)
                #pragma unroll
                for (int j = 0; j < 4; j++) { h[i][j][0] = b0p[j]; h[i][j][1] = b0p[j]; }
            {
                const uint32_t xl = xlane0 + b * X_BUFSZ;
                #pragma unroll
                for (int ks = 0; ks < 3; ks++) {
                    uint32_t a[4][4], bb[2][4];
                    #pragma unroll
                    for (int i = 0; i < 4; i++)
                        ldm_x4(a[i], xl + i * 16 * WS_SMALL + ks * 32);
                    #pragma unroll
                    for (int jj = 0; jj < 2; jj++)
                        ldm_x4(bb[jj], w0lane + jj * 16 * WS_SMALL + ks * 32);
                    #pragma unroll
                    for (int i = 0; i < 4; i++)
                        #pragma unroll
                        for (int jj = 0; jj < 2; jj++) {
                            mma_f16h(h[i][2 * jj],     a[i], bb[jj]);
                            mma_f16h(h[i][2 * jj + 1], a[i], bb[jj] + 2);
                        }
                }
            }
            // relu in place
            #pragma unroll
            for (int i = 0; i < 4; i++)
                #pragma unroll
                for (int j = 0; j < 4; j++) {
                    h[i][j][0] = hmax2_zero(h[i][j][0]);
                    h[i][j][1] = hmax2_zero(h[i][j][1]);
                }

            // ---------- epi0a: per-row max (warp, then cross-warp) ----------
            float rmx[4][2];
            #pragma unroll
            for (int i = 0; i < 4; i++)
                #pragma unroll
                for (int rh = 0; rh < 2; rh++) {
                    __half2 m = __floats2half2_rn(0.f, 0.f);
                    #pragma unroll
                    for (int j = 0; j < 4; j++)
                        m = __hmax2(m, *reinterpret_cast<__half2*>(&h[i][j][rh]));
                    float v = fmaxf(__low2float(m), __high2float(m));
                    v = fmaxf(v, __shfl_xor_sync(0xffffffffu, v, 1));
                    v = fmaxf(v, __shfl_xor_sync(0xffffffffu, v, 2));
                    rmx[i][rh] = v;
                }
            if ((lane & 3) == 0) {
                #pragma unroll
                for (int i = 0; i < 4; i++)
                    #pragma unroll
                    for (int rh = 0; rh < 2; rh++)
                        rowmaxs[(i * 16 + 8 * rh + (lane >> 2)) * 8 + w] = rmx[i][rh];
            }
            bar_sync(BAR_CONS, NCONS);                  // rowmax staged

            // ---------- epi0b: row scale, quantize -> ACTI8 ----------
            float smax[4][2];
            #pragma unroll
            for (int i = 0; i < 4; i++)
                #pragma unroll
                for (int rh = 0; rh < 2; rh++) {
                    const int r = i * 16 + 8 * rh + (lane >> 2);
                    const float4 v0 = *(const float4*)(rowmaxs + r * 8);
                    const float4 v1 = *(const float4*)(rowmaxs + r * 8 + 4);
                    float m = fmaxf(fmaxf(fmaxf(v0.x, v0.y), fmaxf(v0.z, v0.w)),
                                    fmaxf(fmaxf(v1.x, v1.y), fmaxf(v1.z, v1.w)));
                    smax[i][rh] = m * (1.f / 127.f);
                    const float inv = (m > 0.f) ? 127.f / m : 0.f;
                    #pragma unroll
                    for (int j = 0; j < 4; j++) {
                        const float2 f = __half22float2(*reinterpret_cast<__half2*>(&h[i][j][rh]));
                        const int q0 = __float2int_rn(f.x * inv);
                        const int q1 = __float2int_rn(f.y * inv);
                        const int c = nbase + j * 8 + (lane & 3) * 2;
                        *(uint16_t*)(smem + ACTI_OFF + r * WS_I8 + c) =
                            (uint16_t)((q0 & 0xFF) | ((q1 & 0xFF) << 8));
                    }
                }
            bar_sync(BAR_CONS, NCONS);                  // ACTI8 visible
            bar_arrive(BAR_EMPTY0 + b, NTH);            // X buffer free

            // ---------- layer 1: int8 m16n8k32, 8 k-steps ----------
            int32_t acc[4][4][4];
            #pragma unroll
            for (int i = 0; i < 4; i++)
                #pragma unroll
                for (int j = 0; j < 4; j++)
                    #pragma unroll
                    for (int q = 0; q < 4; q++) acc[i][j][q] = 0;
            #pragma unroll
            for (int ks = 0; ks < 8; ks++) {
                uint32_t a[4][4], bb[2][4];
                #pragma unroll
                for (int i = 0; i < 4; i++)
                    ldm_x4(a[i], ailane + i * 16 * WS_I8 + ks * 32);
                #pragma unroll
                for (int jj = 0; jj < 2; jj++)
                    ldm_x4(bb[jj], w1ilane + jj * 16 * WS_I8 + ks * 32);
                #pragma unroll
                for (int i = 0; i < 4; i++)
                    #pragma unroll
                    for (int jj = 0; jj < 2; jj++) {
                        mma_s8(acc[i][2 * jj],     a[i], bb[jj]);
                        mma_s8(acc[i][2 * jj + 1], a[i], bb[jj] + 2);
                    }
            }

            // ---------- dequant + relu + fused layer 2 ----------
            #pragma unroll
            for (int i = 0; i < 4; i++) {
                float pacc[2][3];
                #pragma unroll
                for (int rh = 0; rh < 2; rh++)
                    #pragma unroll
                    for (int c = 0; c < 3; c++) pacc[rh][c] = 0.f;
                #pragma unroll
                for (int j = 0; j < 4; j++)
                    #pragma unroll
                    for (int rh = 0; rh < 2; rh++) {
                        const float sm = smax[i][rh];
                        const float vlo = fmaxf((float)acc[i][j][2 * rh]     * (sm * w1sc[j][0]) + b1r[j][0], 0.f);
                        const float vhi = fmaxf((float)acc[i][j][2 * rh + 1] * (sm * w1sc[j][1]) + b1r[j][1], 0.f);
                        #pragma unroll
                        for (int c = 0; c < 3; c++)
                            pacc[rh][c] += vlo * w2r[j][0][c] + vhi * w2r[j][1][c];
                    }
                #pragma unroll
                for (int rh = 0; rh < 2; rh++)
                    #pragma unroll
                    for (int c = 0; c < 3; c++) {
                        float v = pacc[rh][c];
                        v += __shfl_xor_sync(0xffffffffu, v, 1);
                        v += __shfl_xor_sync(0xffffffffu, v, 2);
                        pacc[rh][c] = v;
                    }
                if ((lane & 3) == 0) {
                    const int r0 = i * 16 + (lane >> 2);
                    #pragma unroll
                    for (int rh = 0; rh < 2; rh++)
                        #pragma unroll
                        for (int c = 0; c < 3; c++)
                            red[(r0 + 8 * rh) * 24 + c * 8 + w] = pacc[rh][c];
                }
            }
            bar_sync(BAR_CONS, NCONS);                  // red staged

            // ---------- final: sum 8 warps, sigmoid, store ----------
            if (t < 192) {
                float s = b2v;
                #pragma unroll
                for (int w8 = 0; w8 < 8; w8++) s += red[fr * 24 + fc * 8 + w8];
                const int gp = tile * PTS + fr;
                if (gp < npts) out[gp * 3 + fc] = 1.f / (1.f + __expf(-s));
            }
        }
    }
}

extern "C" void kernel_launch(void* const* d_in, const int* in_sizes, int n_in,
                              void* d_out, int out_size)
{
    const float* coords = (const float*)d_in[0];
    const float* emb    = (const float*)d_in[1];
    const float* W0     = (const float*)d_in[2];
    const float* b0     = (const float*)d_in[3];
    const float* W1     = (const float*)d_in[4];
    const float* b1     = (const float*)d_in[5];
    const float* W2     = (const float*)d_in[6];
    const float* b2     = (const float*)d_in[7];
    float* out          = (float*)d_out;

    const int npts = in_sizes[0] / 2;

    int dev = 0, nsm = 148;
    cudaGetDevice(&dev);
    cudaDeviceGetAttribute(&nsm, cudaDevAttrMultiProcessorCount, dev);

    cudaFuncSetAttribute(ngp_i8_kernel,
                         cudaFuncAttributeMaxDynamicSharedMemorySize, SMEM_BYTES);

    ngp_i8_kernel<<<nsm, NTH, SMEM_BYTES>>>(coords, emb, W0, b0, W1, b1, W2, b2, out, npts);
}

// round 14
// speedup vs baseline: 2.3588x; 2.3588x over previous
#include <cuda_runtime.h>
#include <cuda_fp16.h>
#include <cstdint>

#define TABLE_SIZE (1u << 19)
#define HASH_MASK  (TABLE_SIZE - 1u)
#define PRIME1     2654435761u
#define NTH        384          // 256 consumer + 128 producer
#define NCONS      256
#define PTS        64

__device__ __constant__ float RES_TAB[16] = {
    16.f, 20.f, 25.f, 32.f, 40.f, 50.f, 64.f, 80.f,
    101.f, 128.f, 161.f, 203.f, 256.f, 322.f, 406.f, 512.f
};

// ---- smem layout (bytes) ----
#define WS_BIG   528             // f16 256-k row stride (layer1 weights / ACT)
#define WS_X     80              // f16 32-k row stride (X and W0)
#define W1T_OFF  0               // [256 n][264] f16 : 135168
#define W0T_OFF  135168          // [256 n][40]  f16 : 20480  (k=2..33 of W0)
#define X_OFF    155648          // 2 x [64 m][40] f16 : 10240
#define X_BUFSZ  5120
#define XY_OFF   165888          // 2 x [64] float2 : 1024
#define ACT_OFF  166912          // [64 m][264] f16 : 33792
#define RED_OFF  200704          // [64 r][3 c][8 w] f32 : 6144
#define SMEM_BYTES 206848

// named barriers
#define BAR_FULL0   1
#define BAR_FULL1   2
#define BAR_EMPTY0  3
#define BAR_EMPTY1  4
#define BAR_CONS    5

__device__ __forceinline__ void bar_sync(int id, int cnt) {
    asm volatile("bar.sync %0, %1;" :: "r"(id), "r"(cnt) : "memory");
}
__device__ __forceinline__ void bar_arrive(int id, int cnt) {
    asm volatile("bar.arrive %0, %1;" :: "r"(id), "r"(cnt) : "memory");
}
__device__ __forceinline__ uint32_t smem_u32(const void* p) {
    uint32_t a;
    asm("{ .reg .u64 t; cvta.to.shared.u64 t, %1; cvt.u32.u64 %0, t; }" : "=r"(a) : "l"(p));
    return a;
}
__device__ __forceinline__ void ldm_x4(uint32_t* r, uint32_t addr) {
    asm volatile("ldmatrix.sync.aligned.m8n8.x4.shared.b16 {%0,%1,%2,%3}, [%4];"
        : "=r"(r[0]), "=r"(r[1]), "=r"(r[2]), "=r"(r[3]) : "r"(addr));
}
__device__ __forceinline__ void mma_f16h(uint32_t* d, const uint32_t* a, const uint32_t* b) {
    asm volatile("mma.sync.aligned.m16n8k16.row.col.f16.f16.f16.f16 "
        "{%0,%1}, {%2,%3,%4,%5}, {%6,%7}, {%0,%1};"
        : "+r"(d[0]), "+r"(d[1])
        : "r"(a[0]), "r"(a[1]), "r"(a[2]), "r"(a[3]), "r"(b[0]), "r"(b[1]));
}
__device__ __forceinline__ uint32_t packh(float lo, float hi) {
    __half2 h = __floats2half2_rn(lo, hi);
    return *reinterpret_cast<uint32_t*>(&h);
}
__device__ __forceinline__ uint32_t hmax2_zero(uint32_t v) {
    __half2 h = *reinterpret_cast<__half2*>(&v);
    __half2 z = __floats2half2_rn(0.f, 0.f);
    __half2 r = __hmax2(h, z);
    return *reinterpret_cast<uint32_t*>(&r);
}
__device__ __forceinline__ uint32_t hfma2_u(uint32_t a, uint32_t b, uint32_t c) {
    __half2 r = __hfma2(*reinterpret_cast<__half2*>(&a),
                        *reinterpret_cast<__half2*>(&b),
                        *reinterpret_cast<__half2*>(&c));
    return *reinterpret_cast<uint32_t*>(&r);
}

extern "C" __global__ void __launch_bounds__(NTH, 1)
ngp_k32_kernel(const float* __restrict__ coords,
               const float* __restrict__ emb,
               const float* __restrict__ W0, const float* __restrict__ b0,
               const float* __restrict__ W1, const float* __restrict__ b1,
               const float* __restrict__ W2, const float* __restrict__ b2,
               float* __restrict__ out, int npts)
{
    extern __shared__ char smem[];
    const uint32_t sb = smem_u32(smem);
    const int t = threadIdx.x;
    const int lane = t & 31;
    const int w = t >> 5;

    // ---- one-time weight staging (f16). W0T holds k-rows 2..33 only. ----
    for (int i = t; i < 256 * 256; i += NTH) {
        const int k = i >> 8, n = i & 255;
        *(__half*)(smem + W1T_OFF + n * WS_BIG + k * 2) = __float2half(W1[i]);
    }
    for (int i = t; i < 32 * 256; i += NTH) {
        const int k = i >> 8, n = i & 255;
        *(__half*)(smem + W0T_OFF + n * WS_X + k * 2) = __float2half(W0[(k + 2) * 256 + n]);
    }
    __syncthreads();

    const int ntiles = (npts + PTS - 1) / PTS;

    if (t >= NCONS) {
        // ============ PRODUCERS: encode (2 threads / point, 8 levels) =======
        const int tp = t - NCONS;
        const int p  = tp >> 1;
        const int g  = tp & 1;
        int iter = 0;
        for (int tile = blockIdx.x; tile < ntiles; tile += gridDim.x, iter++) {
            const int b = iter & 1;
            if (iter >= 2) bar_sync(BAR_EMPTY0 + b, NTH);

            const int gp = tile * PTS + p;
            float2 c = make_float2(0.f, 0.f);
            if (gp < npts) c = ((const float2*)coords)[gp];
            const float x = fminf(fmaxf(c.x, -1.f), 1.f);
            const float y = fminf(fmaxf(c.y, -1.f), 1.f);
            char* xrow = smem + X_OFF + b * X_BUFSZ + p * WS_X;

            if (g == 0)
                ((float2*)(smem + XY_OFF + b * 512))[p] = make_float2(x, y);

            #pragma unroll
            for (int li = 0; li < 8; li++) {
                const int l = g * 8 + li;
                const float res  = RES_TAB[l];
                const float grid = 2.0f / res;
                const float fx = floorf((x + 1.0f) / grid);
                const float fy = floorf((y + 1.0f) / grid);
                const float wx = (x - (fx * grid - 1.0f)) / grid;
                const float wy = (y - (fy * grid - 1.0f)) / grid;
                const unsigned bx = (unsigned)(int)fx;
                const unsigned by = (unsigned)(int)fy;
                const unsigned hy0 = by * PRIME1;
                const unsigned hy1 = (by + 1u) * PRIME1;
                const float2* tabl = (const float2*)emb + (size_t)l * TABLE_SIZE;
                const float2 e00 = tabl[(bx ^ hy0) & HASH_MASK];
                const float2 e01 = tabl[(bx ^ hy1) & HASH_MASK];
                const float2 e10 = tabl[((bx + 1u) ^ hy0) & HASH_MASK];
                const float2 e11 = tabl[((bx + 1u) ^ hy1) & HASH_MASK];
                const float omx = 1.f - wx, omy = 1.f - wy;
                const float f0 = (e00.x * omx + e10.x * wx) * omy + (e01.x * omx + e11.x * wx) * wy;
                const float f1 = (e00.y * omx + e10.y * wx) * omy + (e01.y * omx + e11.y * wx) * wy;
                *(uint32_t*)(xrow + 4 * l) = packh(f0, f1);
            }
            bar_arrive(BAR_FULL0 + b, NTH);
        }
    } else {
        // ============ CONSUMERS: 8 warps, each m64 x n32 ====================
        const int arow  = (lane & 7) + ((lane >> 3) & 1) * 8;
        const int akoff = (lane >> 4) * 8;
        const int bgrp  = ((lane >> 4) << 3) + (lane & 7);
        const int bk16  = ((lane >> 3) & 1) * 16;
        const int nbase = w * 32;

        const uint32_t xlane0 = sb + X_OFF   + arow * WS_X   + akoff * 2;
        const uint32_t alane  = sb + ACT_OFF + arow * WS_BIG + akoff * 2;
        const uint32_t w0lane = sb + W0T_OFF + (nbase + bgrp) * WS_X   + bk16;
        const uint32_t w1lane = sb + W1T_OFF + (nbase + bgrp) * WS_BIG + bk16;

        // preload: b0/b1 (f16x2 C init), xy weight pairs, W2 for this thread's cols
        uint32_t b0p[4], b1p[4], w0x2[4], w0y2[4];
        float w2r[4][2][3];
        #pragma unroll
        for (int j = 0; j < 4; j++) {
            const int n = nbase + j * 8 + 2 * (lane & 3);
            b0p[j]  = packh(b0[n], b0[n + 1]);
            b1p[j]  = packh(b1[n], b1[n + 1]);
            w0x2[j] = packh(W0[n], W0[n + 1]);            // W0 row k=0 (x)
            w0y2[j] = packh(W0[256 + n], W0[256 + n + 1]); // W0 row k=1 (y)
            #pragma unroll
            for (int c = 0; c < 3; c++) {
                w2r[j][0][c] = W2[n * 3 + c];
                w2r[j][1][c] = W2[(n + 1) * 3 + c];
            }
        }
        const int fr = t / 3;
        const int fc = t - 3 * fr;
        const float b2v = (t < 192) ? b2[fc] : 0.f;
        float* red = (float*)(smem + RED_OFF);

        int iter = 0;
        for (int tile = blockIdx.x; tile < ntiles; tile += gridDim.x, iter++) {
            const int b = iter & 1;
            bar_sync(BAR_FULL0 + b, NTH);               // encode(tile) done

            // ---------- layer 0 C-init: bias + x*W0[0] + y*W0[1] ----------
            uint32_t h[4][4][2];
            {
                const float2* xyb = (const float2*)(smem + XY_OFF + b * 512);
                #pragma unroll
                for (int i = 0; i < 4; i++) {
                    const int r0 = i * 16 + (lane >> 2);
                    const float2 p0 = xyb[r0];
                    const float2 p1 = xyb[r0 + 8];
                    const uint32_t x0 = packh(p0.x, p0.x), y0 = packh(p0.y, p0.y);
                    const uint32_t x1 = packh(p1.x, p1.x), y1 = packh(p1.y, p1.y);
                    #pragma unroll
                    for (int j = 0; j < 4; j++) {
                        h[i][j][0] = hfma2_u(y0, w0y2[j], hfma2_u(x0, w0x2[j], b0p[j]));
                        h[i][j][1] = hfma2_u(y1, w0y2[j], hfma2_u(x1, w0x2[j], b0p[j]));
                    }
                }
            }
            // ---------- layer 0: [64,32] @ W0t (2 k-steps) ----------
            {
                const uint32_t xl = xlane0 + b * X_BUFSZ;
                #pragma unroll
                for (int ks = 0; ks < 2; ks++) {
                    uint32_t a[4][4], bb[2][4];
                    #pragma unroll
                    for (int i = 0; i < 4; i++)
                        ldm_x4(a[i], xl + i * 16 * WS_X + ks * 32);
                    #pragma unroll
                    for (int jj = 0; jj < 2; jj++)
                        ldm_x4(bb[jj], w0lane + jj * 16 * WS_X + ks * 32);
                    #pragma unroll
                    for (int i = 0; i < 4; i++)
                        #pragma unroll
                        for (int jj = 0; jj < 2; jj++) {
                            mma_f16h(h[i][2 * jj],     a[i], bb[jj]);
                            mma_f16h(h[i][2 * jj + 1], a[i], bb[jj] + 2);
                        }
                }
            }
            // epi0: relu (hmax2) -> ACT, f16x2 packed
            #pragma unroll
            for (int i = 0; i < 4; i++) {
                const int r0 = i * 16 + (lane >> 2);
                #pragma unroll
                for (int j = 0; j < 4; j++) {
                    const int c = nbase + j * 8 + (lane & 3) * 2;
                    *(uint32_t*)(smem + ACT_OFF + r0 * WS_BIG + c * 2)       = hmax2_zero(h[i][j][0]);
                    *(uint32_t*)(smem + ACT_OFF + (r0 + 8) * WS_BIG + c * 2) = hmax2_zero(h[i][j][1]);
                }
            }
            bar_sync(BAR_CONS, NCONS);                  // full ACT visible
            bar_arrive(BAR_EMPTY0 + b, NTH);            // X buffer free

            // ---------- layer 1: [64,256] @ W1t, bias in C ----------
            #pragma unroll
            for (int i = 0; i < 4; i++)
                #pragma unroll
                for (int j = 0; j < 4; j++) { h[i][j][0] = b1p[j]; h[i][j][1] = b1p[j]; }
            #pragma unroll
            for (int ks = 0; ks < 16; ks++) {
                uint32_t a[4][4], bb[2][4];
                #pragma unroll
                for (int i = 0; i < 4; i++)
                    ldm_x4(a[i], alane + i * 16 * WS_BIG + ks * 32);
                #pragma unroll
                for (int jj = 0; jj < 2; jj++)
                    ldm_x4(bb[jj], w1lane + jj * 16 * WS_BIG + ks * 32);
                #pragma unroll
                for (int i = 0; i < 4; i++)
                    #pragma unroll
                    for (int jj = 0; jj < 2; jj++) {
                        mma_f16h(h[i][2 * jj],     a[i], bb[jj]);
                        mma_f16h(h[i][2 * jj + 1], a[i], bb[jj] + 2);
                    }
            }

            // ---------- fused layer 2: relu in f16, FMA in f32 ----------
            #pragma unroll
            for (int i = 0; i < 4; i++) {
                float pacc[2][3];
                #pragma unroll
                for (int rh = 0; rh < 2; rh++)
                    #pragma unroll
                    for (int c = 0; c < 3; c++) pacc[rh][c] = 0.f;

                #pragma unroll
                for (int j = 0; j < 4; j++) {
                    #pragma unroll
                    for (int rh = 0; rh < 2; rh++) {
                        const uint32_t hr = hmax2_zero(h[i][j][rh]);
                        const __half2 h2 = *reinterpret_cast<const __half2*>(&hr);
                        const float2 f = __half22float2(h2);
                        #pragma unroll
                        for (int c = 0; c < 3; c++)
                            pacc[rh][c] += f.x * w2r[j][0][c] + f.y * w2r[j][1][c];
                    }
                }
                #pragma unroll
                for (int rh = 0; rh < 2; rh++)
                    #pragma unroll
                    for (int c = 0; c < 3; c++) {
                        float v = pacc[rh][c];
                        v += __shfl_xor_sync(0xffffffffu, v, 1);
                        v += __shfl_xor_sync(0xffffffffu, v, 2);
                        pacc[rh][c] = v;
                    }
                if ((lane & 3) == 0) {
                    const int r0 = i * 16 + (lane >> 2);
                    #pragma unroll
                    for (int rh = 0; rh < 2; rh++)
                        #pragma unroll
                        for (int c = 0; c < 3; c++)
                            red[(r0 + 8 * rh) * 24 + c * 8 + w] = pacc[rh][c];
                }
            }
            bar_sync(BAR_CONS, NCONS);                  // red staged

            // ---------- final: sum 8 warps, sigmoid, store ----------
            if (t < 192) {
                float s = b2v;
                #pragma unroll
                for (int w8 = 0; w8 < 8; w8++) s += red[fr * 24 + fc * 8 + w8];
                const int gp = tile * PTS + fr;
                if (gp < npts) out[gp * 3 + fc] = 1.f / (1.f + __expf(-s));
            }
        }
    }
}

extern "C" void kernel_launch(void* const* d_in, const int* in_sizes, int n_in,
                              void* d_out, int out_size)
{
    const float* coords = (const float*)d_in[0];
    const float* emb    = (const float*)d_in[1];
    const float* W0     = (const float*)d_in[2];
    const float* b0     = (const float*)d_in[3];
    const float* W1     = (const float*)d_in[4];
    const float* b1     = (const float*)d_in[5];
    const float* W2     = (const float*)d_in[6];
    const float* b2     = (const float*)d_in[7];
    float* out          = (float*)d_out;

    const int npts = in_sizes[0] / 2;

    int dev = 0, nsm = 148;
    cudaGetDevice(&dev);
    cudaDeviceGetAttribute(&nsm, cudaDevAttrMultiProcessorCount, dev);

    cudaFuncSetAttribute(ngp_k32_kernel,
                         cudaFuncAttributeMaxDynamicSharedMemorySize, SMEM_BYTES);

    ngp_k32_kernel<<<nsm, NTH, SMEM_BYTES>>>(coords, emb, W0, b0, W1, b1, W2, b2, out, npts);
}